// round 2
// baseline (speedup 1.0000x reference)
#include <cuda_runtime.h>

// QuadraticConv2D: out[b,h,w,o] = sum_l sum_c F_l[b,h,w,c] * wk[l,c,o]
//   F: 45 quadratic (triu pairs of the 9 taps), 9 linear taps, 1 bias(=1).
// B=16, H=W=64, C=64, O=64, L=55.  Implicit GEMM M=65536, K=3520, N=64.

#define Bn 16
#define Hn 64
#define Wn 64
#define Cn 64
#define On 64
#define Ln 55

// tap index i in 0..8 -> (row i/3, col i%3); 255 = sentinel
__constant__ unsigned char c_IU[Ln] = {
    0,0,0,0,0,0,0,0,0,
    1,1,1,1,1,1,1,1,
    2,2,2,2,2,2,2,
    3,3,3,3,3,3,
    4,4,4,4,4,
    5,5,5,5,
    6,6,6,
    7,7,
    8,
    0,1,2,3,4,5,6,7,8,   // linear taps
    255                   // bias
};
__constant__ unsigned char c_JU[Ln] = {
    0,1,2,3,4,5,6,7,8,
    1,2,3,4,5,6,7,8,
    2,3,4,5,6,7,8,
    3,4,5,6,7,8,
    4,5,6,7,8,
    5,6,7,8,
    6,7,8,
    7,8,
    8,
    255,255,255,255,255,255,255,255,255,  // linear: no second factor
    255
};

// packed f32x2 helpers (Blackwell FFMA2 — PTX only)
__device__ __forceinline__ void fma2(unsigned long long& d,
                                     unsigned long long a,
                                     unsigned long long b) {
    asm("fma.rn.f32x2 %0, %1, %2, %0;" : "+l"(d) : "l"(a), "l"(b));
}
__device__ __forceinline__ unsigned long long bcast2(float v) {
    unsigned long long r;
    asm("mov.b64 %0, {%1, %1};" : "=l"(r) : "f"(v));
    return r;
}
__device__ __forceinline__ void unpack2(unsigned long long v, float& lo, float& hi) {
    asm("mov.b64 {%0, %1}, %2;" : "=f"(lo), "=f"(hi) : "l"(v));
}

// smem layout (floats):
//   xs : [3][66][64]  = 12672   (3 input rows + w-halo, channel-contiguous)
//   Fs : [64][68]     = 4352    (feature slab, Fs[c][m], padded)
//   Ws : [64][68]     = 4352    (weight slab,  Ws[c][o], padded)
#define XS_F 12672
#define FS_F 4352
#define SMEM_BYTES ((XS_F + 2 * FS_F) * 4)

__global__ __launch_bounds__(256, 2)
void qconv_kernel(const float* __restrict__ x,
                  const float* __restrict__ wk,
                  float* __restrict__ out) {
    extern __shared__ float smem[];
    float* xs = smem;
    float* Fs = smem + XS_F;
    float* Ws = Fs + FS_F;

    const int t  = threadIdx.x;
    const int bh = blockIdx.x;        // b*64 + h
    const int h  = bh & 63;
    const int b  = bh >> 6;

    // ---- load 3 input rows (with zero h-padding) ----
    #pragma unroll
    for (int r = 0; r < 3; ++r) {
        const int hh = h + r - 1;
        float4* d4 = (float4*)(xs + (r * 66 + 1) * 64);
        if (hh >= 0 && hh < Hn) {
            const float4* s4 = (const float4*)(x + ((b * Hn + hh) * Wn) * Cn);
            #pragma unroll
            for (int q = 0; q < 4; ++q) d4[t + q * 256] = s4[t + q * 256];
        } else {
            const float4 z = make_float4(0.f, 0.f, 0.f, 0.f);
            #pragma unroll
            for (int q = 0; q < 4; ++q) d4[t + q * 256] = z;
        }
    }
    // zero the w-halo columns (wcol 0 and 65) : 3 rows * 2 sides * 16 float4
    if (t < 96) {
        const int rr   = t >> 5;          // 0..2
        const int side = (t >> 4) & 1;    // 0..1
        const int c4   = t & 15;
        float4* p = (float4*)(xs + (rr * 66 + (side ? 65 : 0)) * 64 + c4 * 4);
        *p = make_float4(0.f, 0.f, 0.f, 0.f);
    }
    __syncthreads();

    // ---- GEMM thread mapping: 16x16 threads, 4x4 outputs each ----
    const int tx = t & 15;            // -> o
    const int ty = t >> 4;            // -> m (=w)
    const int m0 = ty * 4;
    const int o0 = tx * 4;

    // feature-fill mapping: lanes vary c (bank-friendly), each thread 4 m x 4 c
    const int cbase = t & 15;
    const int mf0   = (t >> 4) * 4;

    // accumulators: 4 m rows x 2 o-pairs, packed f32x2 (zero bits == (0.f,0.f))
    unsigned long long acc[4][2] = {{0ull, 0ull}, {0ull, 0ull}, {0ull, 0ull}, {0ull, 0ull}};

    for (int l = 0; l < Ln; ++l) {
        // --- stage W_l : wk[l, c, o] -> Ws[c][o] ---
        const float4* wsrc = (const float4*)(wk + l * (Cn * On));
        #pragma unroll
        for (int q = 0; q < 4; ++q) {
            const int idx = t + q * 256;      // float4 index 0..1023
            const int c   = idx >> 4;
            const int o4  = idx & 15;
            *(float4*)(Ws + c * 68 + o4 * 4) = wsrc[idx];
        }

        // --- build F_l[c][m] ---
        const int ii = c_IU[l];
        const int jj = c_JU[l];
        if (ii == 255) {
            const float4 one = make_float4(1.f, 1.f, 1.f, 1.f);
            #pragma unroll
            for (int q = 0; q < 4; ++q)
                *(float4*)(Fs + (cbase + q * 16) * 68 + mf0) = one;
        } else {
            const int ri = ii / 3, ci = ii % 3;
            const int offi = (ri * 66 + ci) * 64;
            if (jj == 255) {
                #pragma unroll
                for (int q = 0; q < 4; ++q) {
                    const int c = cbase + q * 16;
                    const float* pi = xs + offi + mf0 * 64 + c;
                    float4 f;
                    f.x = pi[0]; f.y = pi[64]; f.z = pi[128]; f.w = pi[192];
                    *(float4*)(Fs + c * 68 + mf0) = f;
                }
            } else {
                const int rj = jj / 3, cj = jj % 3;
                const int offj = (rj * 66 + cj) * 64;
                #pragma unroll
                for (int q = 0; q < 4; ++q) {
                    const int c = cbase + q * 16;
                    const float* pi = xs + offi + mf0 * 64 + c;
                    const float* pj = xs + offj + mf0 * 64 + c;
                    float4 f;
                    f.x = pi[0]   * pj[0];
                    f.y = pi[64]  * pj[64];
                    f.z = pi[128] * pj[128];
                    f.w = pi[192] * pj[192];
                    *(float4*)(Fs + c * 68 + mf0) = f;
                }
            }
        }
        __syncthreads();

        // --- slab GEMM: acc[m,o] += F[m,c] * W[c,o]  (64 K-steps) ---
        #pragma unroll 16
        for (int c = 0; c < Cn; ++c) {
            const float4 f = *(const float4*)(Fs + c * 68 + m0);
            const ulonglong2 wv = *(const ulonglong2*)(Ws + c * 68 + o0);
            const unsigned long long f0 = bcast2(f.x);
            const unsigned long long f1 = bcast2(f.y);
            const unsigned long long f2 = bcast2(f.z);
            const unsigned long long f3 = bcast2(f.w);
            fma2(acc[0][0], f0, wv.x); fma2(acc[0][1], f0, wv.y);
            fma2(acc[1][0], f1, wv.x); fma2(acc[1][1], f1, wv.y);
            fma2(acc[2][0], f2, wv.x); fma2(acc[2][1], f2, wv.y);
            fma2(acc[3][0], f3, wv.x); fma2(acc[3][1], f3, wv.y);
        }
        __syncthreads();
    }

    // ---- epilogue: out[(bh*64 + m)*64 + o] ----
    #pragma unroll
    for (int mi = 0; mi < 4; ++mi) {
        float4 v;
        unpack2(acc[mi][0], v.x, v.y);
        unpack2(acc[mi][1], v.z, v.w);
        *(float4*)(out + (bh * 64 + (m0 + mi)) * 64 + o0) = v;
    }
}

extern "C" void kernel_launch(void* const* d_in, const int* in_sizes, int n_in,
                              void* d_out, int out_size) {
    const float* x  = (const float*)d_in[0];
    const float* wk = (const float*)d_in[1];   // [1,1,55,64,64] contiguous
    float* out = (float*)d_out;

    cudaFuncSetAttribute(qconv_kernel,
                         cudaFuncAttributeMaxDynamicSharedMemorySize, SMEM_BYTES);
    qconv_kernel<<<Bn * Hn, 256, SMEM_BYTES>>>(x, wk, out);
}

// round 4
// speedup vs baseline: 6.4472x; 6.4472x over previous
#include <cuda_runtime.h>
#include <cuda_fp16.h>
#include <cstdint>

// QuadraticConv2D as implicit GEMM on warp-level fp16 mma.sync (sm_100-safe).
// out[m,o] = sum_{l,c} F_l[m,c] * W[l,c,o];  M=65536, K=54*64 (+exact bias), N=64.
// CTA: 256 thr, 256 m rows (4 image rows of one batch), N=64, all K.
// Warp: m32 x n64; per feature 64x mma.m16n8k16, A fragments computed in regs
// from staged x rows (fp32 product -> fp16), W fp16 staged via cp.async.

#define XS_STRIDE 72                 // fp32 words per w position (conflict-free)
#define XS_ROW    (66 * XS_STRIDE)   // 4752 words per image row (w=-1..64)
#define XS_WORDS  (6 * XS_ROW)       // 28512
#define WS_OFF    (XS_WORDS * 4)     // 114048 B
#define WS_BUF    9216               // one W_l block: 64 o x 72 halfs
#define SMEM_BYTES (WS_OFF + 2 * WS_BUF)   // 132480

// W_l pre-converted fp16, layout [l][o][c] with 72-half row stride.
__device__ __align__(16) __half Wg[54 * 4608];
__device__ float bvecg[64];          // exact bias contribution (fp32)

// feature schedule: grouped by first factor i so xi register cache is reused
__constant__ unsigned char F_I[54] = {
    0,0,0,0,0,0,0,0,0,0,
    1,1,1,1,1,1,1,1,1,
    2,2,2,2,2,2,2,2,
    3,3,3,3,3,3,3,
    4,4,4,4,4,4,
    5,5,5,5,5,
    6,6,6,6,
    7,7,7,
    8,8};
__constant__ unsigned char F_J[54] = {
    0,1,2,3,4,5,6,7,8,255,
    1,2,3,4,5,6,7,8,255,
    2,3,4,5,6,7,8,255,
    3,4,5,6,7,8,255,
    4,5,6,7,8,255,
    5,6,7,8,255,
    6,7,8,255,
    7,8,255,
    8,255};
__constant__ unsigned char F_L[54] = {
    0,1,2,3,4,5,6,7,8,45,
    9,10,11,12,13,14,15,16,46,
    17,18,19,20,21,22,23,47,
    24,25,26,27,28,29,48,
    30,31,32,33,34,49,
    35,36,37,38,50,
    39,40,41,51,
    42,43,52,
    44,53};

static __device__ __forceinline__ void mma16816(float* d,
    uint32_t a0, uint32_t a1, uint32_t a2, uint32_t a3,
    uint32_t b0, uint32_t b1) {
    asm volatile(
        "mma.sync.aligned.m16n8k16.row.col.f32.f16.f16.f32 "
        "{%0,%1,%2,%3}, {%4,%5,%6,%7}, {%8,%9}, {%0,%1,%2,%3};"
        : "+f"(d[0]), "+f"(d[1]), "+f"(d[2]), "+f"(d[3])
        : "r"(a0), "r"(a1), "r"(a2), "r"(a3), "r"(b0), "r"(b1));
}

// -------- prep: W -> fp16 [o][c] padded; bias -> exact fp32 column sums -----
__global__ void prep_W(const float* __restrict__ wk) {
    const int l = blockIdx.x;
    if (l < 54) {
        for (int idx = threadIdx.x; idx < 4096; idx += 256) {
            const int o = idx >> 6, c = idx & 63;
            Wg[l * 4608 + o * 72 + c] = __float2half_rn(wk[l * 4096 + c * 64 + o]);
        }
    } else {
        if (threadIdx.x < 64) {
            float s = 0.f;
            for (int c = 0; c < 64; ++c) s += wk[54 * 4096 + c * 64 + threadIdx.x];
            bvecg[threadIdx.x] = s;
        }
    }
}

// --------------------------------- main -------------------------------------
__global__ __launch_bounds__(256, 1)
void qconv_mma(const float* __restrict__ x, float* __restrict__ out) {
    extern __shared__ float smem[];
    float* xs = smem;
    const uint32_t smem_base = (uint32_t)__cvta_generic_to_shared(smem);
    const uint32_t wsB = smem_base + WS_OFF;

    const int t    = threadIdx.x;
    const int warp = t >> 5, lane = t & 31;
    const int r    = lane >> 2, t4 = lane & 3;
    const int irow = warp >> 1;
    const int wbase = (warp & 1) * 32;
    const int bb = blockIdx.x >> 4;
    const int r0 = (blockIdx.x & 15) * 4;

    // ---- stage 6 x-rows (fp32, stride-72, zero halo) ----
    #pragma unroll
    for (int rr = 0; rr < 6; ++rr) {
        const int hh = r0 + rr - 1;
        if (hh >= 0 && hh < 64) {
            const float4* src = (const float4*)(x + (size_t)(bb * 64 + hh) * 4096);
            #pragma unroll
            for (int k = 0; k < 4; ++k) {
                const int idx = t + k * 256;          // 0..1023 float4s
                const int ww = idx >> 4, c4 = idx & 15;
                *(float4*)(xs + rr * XS_ROW + (ww + 1) * XS_STRIDE + c4 * 4) = src[idx];
            }
        } else {
            const float4 z = make_float4(0.f, 0.f, 0.f, 0.f);
            #pragma unroll
            for (int k = 0; k < 4; ++k) {
                const int idx = t + k * 256;
                const int ww = idx >> 4, c4 = idx & 15;
                *(float4*)(xs + rr * XS_ROW + (ww + 1) * XS_STRIDE + c4 * 4) = z;
            }
        }
    }
    if (t < 192) {
        const int rr = t >> 5, side = (t >> 4) & 1, c4 = t & 15;
        *(float4*)(xs + rr * XS_ROW + (side ? 65 : 0) * XS_STRIDE + c4 * 4) =
            make_float4(0.f, 0.f, 0.f, 0.f);
    }

    // ---- stage W for feature 0 ----
    {
        const char* src = (const char*)Wg + (int)F_L[0] * WS_BUF;
        #pragma unroll
        for (int k = 0; k < 3; ++k) {
            const int idx = t + k * 256;
            if (idx < 576)
                asm volatile("cp.async.ca.shared.global [%0], [%1], 16;"
                             :: "r"(wsB + idx * 16), "l"(src + idx * 16) : "memory");
        }
        asm volatile("cp.async.commit_group;" ::: "memory");
    }

    float acc[2][8][4];
    #pragma unroll
    for (int a = 0; a < 2; ++a)
        #pragma unroll
        for (int b = 0; b < 8; ++b)
            #pragma unroll
            for (int cc = 0; cc < 4; ++cc) acc[a][b][cc] = 0.f;

    float2 xi[4][8];
    int cur_i = -1;

    for (int f = 0; f < 54; ++f) {
        if (f < 53) {
            const char* src = (const char*)Wg + (int)F_L[f + 1] * WS_BUF;
            const uint32_t dst = wsB + ((f + 1) & 1) * WS_BUF;
            #pragma unroll
            for (int k = 0; k < 3; ++k) {
                const int idx = t + k * 256;
                if (idx < 576)
                    asm volatile("cp.async.ca.shared.global [%0], [%1], 16;"
                                 :: "r"(dst + idx * 16), "l"(src + idx * 16) : "memory");
            }
            asm volatile("cp.async.commit_group;" ::: "memory");
            asm volatile("cp.async.wait_group 1;" ::: "memory");
        } else {
            asm volatile("cp.async.wait_group 0;" ::: "memory");
        }
        __syncthreads();

        const int ii = F_I[f], jj = F_J[f];

        if (ii != cur_i) {                       // reload xi register cache
            cur_i = ii;
            const int di = ii / 3, dj = ii % 3;
            #pragma unroll
            for (int mi = 0; mi < 4; ++mi) {
                const float* base = xs + (irow + di) * XS_ROW
                                  + (wbase + mi * 8 + r + dj) * XS_STRIDE + 2 * t4;
                #pragma unroll
                for (int p = 0; p < 8; ++p) xi[mi][p] = *(const float2*)(base + 8 * p);
            }
        }

        const uint32_t wbuf = wsB + (f & 1) * WS_BUF;
        const bool quad = (jj != 255);
        const float* jb[4];
        if (quad) {
            const int dr = jj / 3, dc = jj % 3;
            #pragma unroll
            for (int mi = 0; mi < 4; ++mi)
                jb[mi] = xs + (irow + dr) * XS_ROW
                       + (wbase + mi * 8 + r + dc) * XS_STRIDE + 2 * t4;
        }

        #pragma unroll
        for (int q = 0; q < 4; ++q) {
            uint32_t b0[8], b1[8];
            #pragma unroll
            for (int nt = 0; nt < 8; ++nt) {
                const uint32_t ad = wbuf + (nt * 8 + r) * 144 + q * 32 + t4 * 4;
                asm volatile("ld.shared.b32 %0, [%1];" : "=r"(b0[nt]) : "r"(ad));
                asm volatile("ld.shared.b32 %0, [%1];" : "=r"(b1[nt]) : "r"(ad + 16));
            }
            uint32_t ha[4][2];
            #pragma unroll
            for (int mi = 0; mi < 4; ++mi) {
                float2 plo = xi[mi][2 * q], phi = xi[mi][2 * q + 1];
                if (quad) {
                    const float2 jlo = *(const float2*)(jb[mi] + 16 * q);
                    const float2 jhi = *(const float2*)(jb[mi] + 16 * q + 8);
                    plo.x *= jlo.x; plo.y *= jlo.y;
                    phi.x *= jhi.x; phi.y *= jhi.y;
                }
                __half2 hlo = __floats2half2_rn(plo.x, plo.y);
                __half2 hhi = __floats2half2_rn(phi.x, phi.y);
                ha[mi][0] = *(uint32_t*)&hlo;
                ha[mi][1] = *(uint32_t*)&hhi;
            }
            #pragma unroll
            for (int nt = 0; nt < 8; ++nt) {
                mma16816(acc[0][nt], ha[0][0], ha[1][0], ha[0][1], ha[1][1],
                         b0[nt], b1[nt]);
                mma16816(acc[1][nt], ha[2][0], ha[3][0], ha[2][1], ha[3][1],
                         b0[nt], b1[nt]);
            }
        }
        if (f < 53) __syncthreads();
    }

    // ---- epilogue: exact bias add + coalesced-enough float2 stores ----
    const int mrow0 = blockIdx.x * 256 + warp * 32 + r;
    #pragma unroll
    for (int mt = 0; mt < 2; ++mt) {
        #pragma unroll
        for (int nt = 0; nt < 8; ++nt) {
            const int n = nt * 8 + t4 * 2;
            const float bvx = bvecg[n], bvy = bvecg[n + 1];
            float* o0 = out + (size_t)(mrow0 + mt * 16) * 64 + n;
            float2 v0 = make_float2(acc[mt][nt][0] + bvx, acc[mt][nt][1] + bvy);
            float2 v1 = make_float2(acc[mt][nt][2] + bvx, acc[mt][nt][3] + bvy);
            *(float2*)o0 = v0;
            *(float2*)(o0 + 8 * 64) = v1;
        }
    }
}

extern "C" void kernel_launch(void* const* d_in, const int* in_sizes, int n_in,
                              void* d_out, int out_size) {
    const float* x  = (const float*)d_in[0];
    const float* wk = (const float*)d_in[1];   // [55,64,64] (l,c,o) contiguous
    float* out = (float*)d_out;

    prep_W<<<55, 256>>>(wk);
    cudaFuncSetAttribute(qconv_mma,
                         cudaFuncAttributeMaxDynamicSharedMemorySize, SMEM_BYTES);
    qconv_mma<<<256, 256, SMEM_BYTES>>>(x, out);
}

// round 5
// speedup vs baseline: 7.2329x; 1.1219x over previous
#include <cuda_runtime.h>
#include <cuda_fp16.h>
#include <cstdint>

// QuadraticConv2D as implicit GEMM on warp-level fp16 mma.sync (sm_100-safe).
// out[m,o] = sum_{l,c} F_l[m,c] * W[l,c,o];  M=65536, K=54*64 (+exact bias), N=64.
// CTA: 256 thr, 256 m rows (4 image rows), N=64, all K. Warp: m32 x n64.
// x staged in smem as fp16 (57KB); A fragments = HMUL2 of register-cached taps.
// W fp16 via 4-deep cp.async ring (36KB); one __syncthreads per feature.
// 2 CTAs/SM (94KB smem, <=128 regs).

#define XS_STRIDE 72                    // halfs per w position (conflict-free)
#define XS_ROW    (66 * XS_STRIDE)      // 4752 halfs per image row
#define XS_HALFS  (6 * XS_ROW)          // 28512
#define WS_OFF    (XS_HALFS * 2)        // 57024 B
#define WS_BUF    9216                  // one W_l block: 64 o x 72 halfs
#define NBUF      4
#define SMEM_BYTES (WS_OFF + NBUF * WS_BUF)   // 93888

// W_l pre-converted fp16, layout [l][o][c] with 72-half row stride.
__device__ __align__(16) __half Wg[54 * 4608];
__device__ float bvecg[64];             // exact bias contribution (fp32)

__constant__ unsigned char F_I[54] = {
    0,0,0,0,0,0,0,0,0,0, 1,1,1,1,1,1,1,1,1, 2,2,2,2,2,2,2,2,
    3,3,3,3,3,3,3, 4,4,4,4,4,4, 5,5,5,5,5, 6,6,6,6, 7,7,7, 8,8};
__constant__ unsigned char F_J[54] = {
    0,1,2,3,4,5,6,7,8,255, 1,2,3,4,5,6,7,8,255, 2,3,4,5,6,7,8,255,
    3,4,5,6,7,8,255, 4,5,6,7,8,255, 5,6,7,8,255, 6,7,8,255, 7,8,255, 8,255};
__constant__ unsigned char F_L[54] = {
    0,1,2,3,4,5,6,7,8,45, 9,10,11,12,13,14,15,16,46, 17,18,19,20,21,22,23,47,
    24,25,26,27,28,29,48, 30,31,32,33,34,49, 35,36,37,38,50,
    39,40,41,51, 42,43,52, 44,53};

static __device__ __forceinline__ void mma16816(float* d,
    uint32_t a0, uint32_t a1, uint32_t a2, uint32_t a3,
    uint32_t b0, uint32_t b1) {
    asm volatile(
        "mma.sync.aligned.m16n8k16.row.col.f32.f16.f16.f32 "
        "{%0,%1,%2,%3}, {%4,%5,%6,%7}, {%8,%9}, {%0,%1,%2,%3};"
        : "+f"(d[0]), "+f"(d[1]), "+f"(d[2]), "+f"(d[3])
        : "r"(a0), "r"(a1), "r"(a2), "r"(a3), "r"(b0), "r"(b1));
}

__global__ void prep_W(const float* __restrict__ wk) {
    const int l = blockIdx.x;
    if (l < 54) {
        for (int idx = threadIdx.x; idx < 4096; idx += 256) {
            const int o = idx >> 6, c = idx & 63;
            Wg[l * 4608 + o * 72 + c] = __float2half_rn(wk[l * 4096 + c * 64 + o]);
        }
    } else if (threadIdx.x < 64) {
        float s = 0.f;
        for (int c = 0; c < 64; ++c) s += wk[54 * 4096 + c * 64 + threadIdx.x];
        bvecg[threadIdx.x] = s;
    }
}

static __device__ __forceinline__ void issue_w_cp(uint32_t dst, int l, int t) {
    const char* src = (const char*)Wg + (size_t)F_L[l] * WS_BUF;
    asm volatile("cp.async.ca.shared.global [%0], [%1], 16;"
                 :: "r"(dst + t * 16), "l"(src + t * 16) : "memory");
    asm volatile("cp.async.ca.shared.global [%0], [%1], 16;"
                 :: "r"(dst + (t + 256) * 16), "l"(src + (t + 256) * 16) : "memory");
    if (t < 64)
        asm volatile("cp.async.ca.shared.global [%0], [%1], 16;"
                     :: "r"(dst + (t + 512) * 16), "l"(src + (t + 512) * 16) : "memory");
    asm volatile("cp.async.commit_group;" ::: "memory");
}

__global__ __launch_bounds__(256, 2)
void qconv_mma(const float* __restrict__ x, float* __restrict__ out) {
    extern __shared__ __half xsm[];
    __half* xs = xsm;
    const uint32_t smem_base = (uint32_t)__cvta_generic_to_shared(xsm);
    const uint32_t wsB = smem_base + WS_OFF;

    const int t    = threadIdx.x;
    const int warp = t >> 5, lane = t & 31;
    const int r    = lane >> 2, t4 = lane & 3;
    const int irow = warp >> 1;
    const int wbase = (warp & 1) * 32;
    const int bb = blockIdx.x >> 4;
    const int r0 = (blockIdx.x & 15) * 4;

    // ---- stage 6 x-rows as fp16 (stride-72, zero halo) ----
    #pragma unroll
    for (int rr = 0; rr < 6; ++rr) {
        const int hh = r0 + rr - 1;
        if (hh >= 0 && hh < 64) {
            const float4* src = (const float4*)(x + (size_t)(bb * 64 + hh) * 4096);
            #pragma unroll
            for (int k = 0; k < 4; ++k) {
                const int idx = t + k * 256;          // float4 idx 0..1023
                const int ww = idx >> 4, c4 = idx & 15;
                const float4 v = src[idx];
                const __half2 h0 = __floats2half2_rn(v.x, v.y);
                const __half2 h1 = __floats2half2_rn(v.z, v.w);
                uint2 pk;
                pk.x = *(const uint32_t*)&h0;
                pk.y = *(const uint32_t*)&h1;
                *(uint2*)(xs + rr * XS_ROW + (ww + 1) * XS_STRIDE + c4 * 4) = pk;
            }
        } else {
            const uint2 z = make_uint2(0u, 0u);
            #pragma unroll
            for (int k = 0; k < 4; ++k) {
                const int idx = t + k * 256;
                const int ww = idx >> 4, c4 = idx & 15;
                *(uint2*)(xs + rr * XS_ROW + (ww + 1) * XS_STRIDE + c4 * 4) = z;
            }
        }
    }
    if (t < 192) {
        const int rr = t >> 5, side = (t >> 4) & 1, c4 = t & 15;
        *(uint2*)(xs + rr * XS_ROW + (side ? 65 : 0) * XS_STRIDE + c4 * 4) =
            make_uint2(0u, 0u);
    }

    // ---- W prefetch: features 0..2 into ring buffers 0..2 ----
    issue_w_cp(wsB + 0 * WS_BUF, 0, t);
    issue_w_cp(wsB + 1 * WS_BUF, 1, t);
    issue_w_cp(wsB + 2 * WS_BUF, 2, t);

    float acc[2][8][4];
    #pragma unroll
    for (int a = 0; a < 2; ++a)
        #pragma unroll
        for (int b = 0; b < 8; ++b)
            #pragma unroll
            for (int cc = 0; cc < 4; ++cc) acc[a][b][cc] = 0.f;

    uint32_t xi[4][8];          // half2 tap cache (factor i)
    int cur_i = -1;

    for (int f = 0; f < 54; ++f) {
        if (f < 52)       asm volatile("cp.async.wait_group 2;" ::: "memory");
        else if (f == 52) asm volatile("cp.async.wait_group 1;" ::: "memory");
        else              asm volatile("cp.async.wait_group 0;" ::: "memory");
        __syncthreads();    // W[f] visible; buffer (f+3)&3 free for reuse

        if (f + 3 < 54) issue_w_cp(wsB + ((f + 3) & 3) * WS_BUF, f + 3, t);

        const int ii = F_I[f], jj = F_J[f];

        if (ii != cur_i) {
            cur_i = ii;
            const int di = ii / 3, dj = ii % 3;
            #pragma unroll
            for (int mi = 0; mi < 4; ++mi) {
                const __half* base = xs + (irow + di) * XS_ROW
                                   + (wbase + mi * 8 + r + dj) * XS_STRIDE + 2 * t4;
                #pragma unroll
                for (int p = 0; p < 8; ++p)
                    xi[mi][p] = *(const uint32_t*)(base + 8 * p);
            }
        }

        const char* wbuf = (const char*)xs + WS_OFF + (f & 3) * WS_BUF;
        const bool quad = (jj != 255);
        const __half* jb[4];
        if (quad) {
            const int dr = jj / 3, dc = jj % 3;
            #pragma unroll
            for (int mi = 0; mi < 4; ++mi)
                jb[mi] = xs + (irow + dr) * XS_ROW
                       + (wbase + mi * 8 + r + dc) * XS_STRIDE + 2 * t4;
        }

        #pragma unroll
        for (int q = 0; q < 4; ++q) {
            uint32_t b0[8], b1[8];
            #pragma unroll
            for (int nt = 0; nt < 8; ++nt) {
                const char* ad = wbuf + (nt * 8 + r) * 144 + q * 32 + t4 * 4;
                b0[nt] = *(const uint32_t*)ad;
                b1[nt] = *(const uint32_t*)(ad + 16);
            }
            uint32_t ha[4][2];
            #pragma unroll
            for (int mi = 0; mi < 4; ++mi) {
                if (quad) {
                    const uint32_t j0 = *(const uint32_t*)(jb[mi] + 16 * q);
                    const uint32_t j1 = *(const uint32_t*)(jb[mi] + 16 * q + 8);
                    const __half2 p0 = __hmul2(*(const __half2*)&xi[mi][2 * q],
                                               *(const __half2*)&j0);
                    const __half2 p1 = __hmul2(*(const __half2*)&xi[mi][2 * q + 1],
                                               *(const __half2*)&j1);
                    ha[mi][0] = *(const uint32_t*)&p0;
                    ha[mi][1] = *(const uint32_t*)&p1;
                } else {
                    ha[mi][0] = xi[mi][2 * q];
                    ha[mi][1] = xi[mi][2 * q + 1];
                }
            }
            #pragma unroll
            for (int nt = 0; nt < 8; ++nt) {
                mma16816(acc[0][nt], ha[0][0], ha[1][0], ha[0][1], ha[1][1],
                         b0[nt], b1[nt]);
                mma16816(acc[1][nt], ha[2][0], ha[3][0], ha[2][1], ha[3][1],
                         b0[nt], b1[nt]);
            }
        }
    }

    // ---- epilogue: exact bias add + float2 stores ----
    const int mrow0 = blockIdx.x * 256 + warp * 32 + r;
    #pragma unroll
    for (int mt = 0; mt < 2; ++mt) {
        #pragma unroll
        for (int nt = 0; nt < 8; ++nt) {
            const int n = nt * 8 + t4 * 2;
            const float bvx = bvecg[n], bvy = bvecg[n + 1];
            float* o0 = out + (size_t)(mrow0 + mt * 16) * 64 + n;
            *(float2*)o0 = make_float2(acc[mt][nt][0] + bvx, acc[mt][nt][1] + bvy);
            *(float2*)(o0 + 8 * 64) =
                make_float2(acc[mt][nt][2] + bvx, acc[mt][nt][3] + bvy);
        }
    }
}

extern "C" void kernel_launch(void* const* d_in, const int* in_sizes, int n_in,
                              void* d_out, int out_size) {
    const float* x  = (const float*)d_in[0];
    const float* wk = (const float*)d_in[1];   // [55,64,64] (l,c,o) contiguous
    float* out = (float*)d_out;

    prep_W<<<55, 256>>>(wk);
    cudaFuncSetAttribute(qconv_mma,
                         cudaFuncAttributeMaxDynamicSharedMemorySize, SMEM_BYTES);
    qconv_mma<<<256, 256, SMEM_BYTES>>>(x, out);
}